// round 14
// baseline (speedup 1.0000x reference)
#include <cuda_runtime.h>
#include <cuda_bf16.h>
#include <mma.h>
using namespace nvcuda;

#define NN 50000
#define NN_PAD 50048   // 782 * 64
#define NE 800000
#define CIN 128
#define CHID 128
#define COUT 64
#define NB 196         // ceil(NN/256)

// ---------------- scratch (static device globals; host uses cudaGetSymbolAddress) ----------------
__device__ __align__(16) int   g_cnt[NN];
__device__ __align__(16) int   g_fpos[NN];
__device__ __align__(16) int   g_tmp[NN];
__device__ __align__(16) int   g_bsum[256];
__device__ __align__(16) int   g_s32[NE];
__device__ __align__(16) int   g_d32[NE];
__device__ __align__(16) int   g_csr[NE];
__device__ __align__(16) float g_wcsr[NE];
__device__ __align__(16) float g_dinv[NN];
__device__ __align__(16) float g_invdeg[NN];
__device__ __align__(16) __nv_bfloat16 g_xb[(size_t)NN_PAD * CIN];
__device__ __align__(16) __nv_bfloat16 g_W1b[CIN * CHID];
__device__ __align__(16) float g_hW[(size_t)NN_PAD * CHID];          // x @ W1 (f32)
__device__ __align__(16) float g_z0[(size_t)NN * COUT];              // conv1 out @ W2 (f32)
__device__ __align__(16) __nv_bfloat16 g_zb[(size_t)NN * COUT];      // bf16(z)
__device__ __align__(16) __nv_bfloat16 g_ub[(size_t)NN * COUT];      // bf16(z @ Wb)
__device__ int g_is64;

// bf16 RNE rounding kept in f32 (XLA BF16_BF16_F32 operand semantics)
__device__ __forceinline__ float bfq(float x) {
    return __bfloat162float(__float2bfloat16_rn(x));
}

__device__ __forceinline__ int eidx(const void* ei, unsigned idx, int is64) {
    if (is64) return (int)((const long long*)ei)[idx];
    return ((const int*)ei)[idx];
}

// ---------------- setup: probe dtype, zero counters ----------------
__global__ void k_setup(const int* __restrict__ ei32, int* __restrict__ cnt,
                        int* __restrict__ fpos, int* __restrict__ is64p) {
    int i = blockIdx.x * blockDim.x + threadIdx.x;
    if (i == 0) {
        int is64 = 1;
        for (int k = 1; k < 128; k += 2)
            if (ei32[k] != 0) { is64 = 0; break; }
        *is64p = is64;
    }
    if (i < NN) { cnt[i] = 0; fpos[i] = 0; }
}

__global__ void k_prep(const void* __restrict__ ei, int* __restrict__ s32,
                       int* __restrict__ d32, int* __restrict__ cnt,
                       const int* __restrict__ is64p) {
    int e = blockIdx.x * blockDim.x + threadIdx.x;
    if (e >= NE) return;
    int is64 = *is64p;
    int s = eidx(ei, e, is64);
    int d = eidx(ei, NE + e, is64);
    s32[e] = s;
    d32[e] = d;
    atomicAdd(&cnt[d], 1);
}

// block-local exclusive scan + per-node dinv/invdeg
__global__ void k_scan1(const int* __restrict__ cnt, int* __restrict__ tmp,
                        int* __restrict__ bsum, float* __restrict__ dinv,
                        float* __restrict__ invdeg) {
    __shared__ int sh[256];
    int i = blockIdx.x * 256 + threadIdx.x;
    int v = (i < NN) ? cnt[i] : 0;
    if (i < NN) {
        float deg = (float)(v + 1);
        dinv[i] = rsqrtf(deg);
        invdeg[i] = 1.0f / deg;
    }
    sh[threadIdx.x] = v;
    __syncthreads();
    for (int off = 1; off < 256; off <<= 1) {
        int t = (threadIdx.x >= off) ? sh[threadIdx.x - off] : 0;
        __syncthreads();
        sh[threadIdx.x] += t;
        __syncthreads();
    }
    if (i < NN) tmp[i] = sh[threadIdx.x] - v;
    if (threadIdx.x == 255) bsum[blockIdx.x] = sh[255];
}

__global__ void k_scan2(int* __restrict__ bsum) {
    __shared__ int sh[256];
    int v = (threadIdx.x < NB) ? bsum[threadIdx.x] : 0;
    sh[threadIdx.x] = v;
    __syncthreads();
    for (int off = 1; off < 256; off <<= 1) {
        int t = (threadIdx.x >= off) ? sh[threadIdx.x - off] : 0;
        __syncthreads();
        sh[threadIdx.x] += t;
        __syncthreads();
    }
    if (threadIdx.x < NB) bsum[threadIdx.x] = sh[threadIdx.x] - v;
}

// bucket-fill CSR (rp computed inline) + precomputed edge weight
__global__ void k_fill(const int* __restrict__ s32, const int* __restrict__ d32,
                       const int* __restrict__ tmp, const int* __restrict__ bsum,
                       int* __restrict__ fpos, int* __restrict__ csr,
                       float* __restrict__ wcsr, const float* __restrict__ dinv) {
    int e = blockIdx.x * blockDim.x + threadIdx.x;
    if (e >= NE) return;
    int s = s32[e];
    int d = d32[e];
    int rp = tmp[d] + bsum[d >> 8];
    int pos = rp + atomicAdd(&fpos[d], 1);
    csr[pos] = s;
    wcsr[pos] = dinv[s] * dinv[d];
}

// ---------------- conversions ----------------
__global__ void k_cvt8(const float* __restrict__ src, __nv_bfloat16* __restrict__ dst,
                       int n_valid, int n_total) {
    int base = (blockIdx.x * blockDim.x + threadIdx.x) * 8;
    if (base >= n_total) return;
    uint4 o;
    if (base < n_valid) {
        float4 a = *(const float4*)(src + base);
        float4 b = *(const float4*)(src + base + 4);
        __nv_bfloat162 p0 = __floats2bfloat162_rn(a.x, a.y);
        __nv_bfloat162 p1 = __floats2bfloat162_rn(a.z, a.w);
        __nv_bfloat162 p2 = __floats2bfloat162_rn(b.x, b.y);
        __nv_bfloat162 p3 = __floats2bfloat162_rn(b.z, b.w);
        o.x = *(unsigned*)&p0; o.y = *(unsigned*)&p1;
        o.z = *(unsigned*)&p2; o.w = *(unsigned*)&p3;
    } else {
        o = make_uint4(0, 0, 0, 0);
    }
    *(uint4*)(dst + base) = o;
}

__global__ void k_cvtW1(const float* __restrict__ W1, __nv_bfloat16* __restrict__ W1b) {
    int i = blockIdx.x * blockDim.x + threadIdx.x;
    if (i < CIN * CHID) W1b[i] = __float2bfloat16_rn(W1[i]);
}

// ------- tensor-core GEMM1: hW[NN_PAD,CHID] = xb @ W1b, f32 accum -------
__global__ void k_wgemm1(const __nv_bfloat16* __restrict__ A,
                         const __nv_bfloat16* __restrict__ W,
                         float* __restrict__ out) {
    __shared__ __nv_bfloat16 Ws[CIN * CHID];
    int tid = threadIdx.x;
    for (int i = tid * 8; i < CIN * CHID; i += blockDim.x * 8)
        *(uint4*)(Ws + i) = *(const uint4*)(W + i);
    __syncthreads();
    int warp = tid >> 5;
    size_t row0 = (size_t)blockIdx.x * 64 + warp * 16;
    wmma::fragment<wmma::accumulator, 16, 16, 16, float> acc[CHID / 16];
#pragma unroll
    for (int n = 0; n < CHID / 16; n++) wmma::fill_fragment(acc[n], 0.f);
#pragma unroll
    for (int k0 = 0; k0 < CIN; k0 += 16) {
        wmma::fragment<wmma::matrix_a, 16, 16, 16, __nv_bfloat16, wmma::row_major> af;
        wmma::load_matrix_sync(af, A + row0 * CIN + k0, CIN);
#pragma unroll
        for (int n = 0; n < CHID / 16; n++) {
            wmma::fragment<wmma::matrix_b, 16, 16, 16, __nv_bfloat16, wmma::row_major> bf;
            wmma::load_matrix_sync(bf, Ws + k0 * CHID + n * 16, CHID);
            wmma::mma_sync(acc[n], af, bf, acc[n]);
        }
    }
#pragma unroll
    for (int n = 0; n < CHID / 16; n++)
        wmma::store_matrix_sync(out + row0 * CHID + n * 16, acc[n], CHID, wmma::mem_row_major);
}

// ------- conv1 fused: CSR gather (128ch) + relu/bias + GEMM2 -> z0 (f32) -------
// one warp per node; W2 staged bf16-rounded f32, transposed [c][k] padded to 129.
__global__ __launch_bounds__(256) void k_conv1(
        const int* __restrict__ tmp, const int* __restrict__ bsum,
        const int* __restrict__ cnt, const int* __restrict__ csr,
        const float* __restrict__ wcsr, const float* __restrict__ hW,
        const float* __restrict__ invdeg, const float* __restrict__ b1,
        const float* __restrict__ W2, float* __restrict__ z0) {
    __shared__ float W2t[COUT][CIN + 1];   // [c][k], bf16-rounded, padded
    __shared__ float hrow[8][CHID];        // per-warp staged h row (bf16-rounded)
    int tid = threadIdx.x;
    for (int i = tid; i < CHID * COUT; i += 256) {
        int k = i / COUT, c = i - k * COUT;
        W2t[c][k] = bfq(W2[i]);
    }
    __syncthreads();
    int warp = (blockIdx.x * 256 + tid) >> 5;
    int lane = tid & 31;
    int w = (tid >> 5);
    if (warp >= NN) return;
    int node = warp;
    int n = cnt[node];
    int base = tmp[node] + bsum[node >> 8];
    float4 acc = make_float4(0.f, 0.f, 0.f, 0.f);
    int j = 0;
    for (; j + 4 <= n; j += 4) {
        int s0 = csr[base + j],     s1 = csr[base + j + 1];
        int s2 = csr[base + j + 2], s3 = csr[base + j + 3];
        float w0 = wcsr[base + j],     w1 = wcsr[base + j + 1];
        float w2 = wcsr[base + j + 2], w3 = wcsr[base + j + 3];
        float4 v0 = ((const float4*)(hW + (size_t)s0 * CHID))[lane];
        float4 v1 = ((const float4*)(hW + (size_t)s1 * CHID))[lane];
        float4 v2 = ((const float4*)(hW + (size_t)s2 * CHID))[lane];
        float4 v3 = ((const float4*)(hW + (size_t)s3 * CHID))[lane];
        acc.x += v0.x * w0 + v1.x * w1 + v2.x * w2 + v3.x * w3;
        acc.y += v0.y * w0 + v1.y * w1 + v2.y * w2 + v3.y * w3;
        acc.z += v0.z * w0 + v1.z * w1 + v2.z * w2 + v3.z * w3;
        acc.w += v0.w * w0 + v1.w * w1 + v2.w * w2 + v3.w * w3;
    }
    for (; j < n; j++) {
        int s0 = csr[base + j];
        float w0 = wcsr[base + j];
        float4 v0 = ((const float4*)(hW + (size_t)s0 * CHID))[lane];
        acc.x += v0.x * w0; acc.y += v0.y * w0;
        acc.z += v0.z * w0; acc.w += v0.w * w0;
    }
    float idg = invdeg[node];
    float4 p = ((const float4*)(hW + (size_t)node * CHID))[lane];
    float4 bv = ((const float4*)b1)[lane];
    // h = relu(agg + self + bias), bf16-rounded as GEMM2 operand
    hrow[w][lane * 4 + 0] = bfq(fmaxf(fmaf(p.x, idg, acc.x) + bv.x, 0.f));
    hrow[w][lane * 4 + 1] = bfq(fmaxf(fmaf(p.y, idg, acc.y) + bv.y, 0.f));
    hrow[w][lane * 4 + 2] = bfq(fmaxf(fmaf(p.z, idg, acc.z) + bv.z, 0.f));
    hrow[w][lane * 4 + 3] = bfq(fmaxf(fmaf(p.w, idg, acc.w) + bv.w, 0.f));
    __syncwarp();
    // z0[node][c] for c = lane, lane+32
    float a0 = 0.f, a1 = 0.f;
#pragma unroll 4
    for (int k = 0; k < CHID; k++) {
        float hk = hrow[w][k];
        a0 = fmaf(hk, W2t[lane][k], a0);
        a1 = fmaf(hk, W2t[lane + 32][k], a1);
    }
    z0[(size_t)node * COUT + lane] = a0;
    z0[(size_t)node * COUT + lane + 32] = a1;
}

// ------- conv2 fused: CSR gather (64ch) + bias + GEMM3 -> zb, ub (bf16) -------
__global__ __launch_bounds__(256) void k_conv2(
        const int* __restrict__ tmp, const int* __restrict__ bsum,
        const int* __restrict__ cnt, const int* __restrict__ csr,
        const float* __restrict__ wcsr, const float* __restrict__ z0,
        const float* __restrict__ invdeg, const float* __restrict__ b2,
        const float* __restrict__ Wb, __nv_bfloat16* __restrict__ zb,
        __nv_bfloat16* __restrict__ ub) {
    __shared__ float Wbt[COUT][COUT + 1];  // [c][k], bf16-rounded
    __shared__ float zrow[8][COUT];        // per-warp staged z row (bf16-rounded)
    int tid = threadIdx.x;
    for (int i = tid; i < COUT * COUT; i += 256) {
        int k = i / COUT, c = i - k * COUT;
        Wbt[c][k] = bfq(Wb[i]);
    }
    __syncthreads();
    int warp = (blockIdx.x * 256 + tid) >> 5;
    int lane = tid & 31;
    int w = (tid >> 5);
    if (warp >= NN) return;
    int node = warp;
    int n = cnt[node];
    int base = tmp[node] + bsum[node >> 8];
    float2 acc = make_float2(0.f, 0.f);
    int j = 0;
    for (; j + 4 <= n; j += 4) {
        int s0 = csr[base + j],     s1 = csr[base + j + 1];
        int s2 = csr[base + j + 2], s3 = csr[base + j + 3];
        float w0 = wcsr[base + j],     w1 = wcsr[base + j + 1];
        float w2 = wcsr[base + j + 2], w3 = wcsr[base + j + 3];
        float2 v0 = ((const float2*)(z0 + (size_t)s0 * COUT))[lane];
        float2 v1 = ((const float2*)(z0 + (size_t)s1 * COUT))[lane];
        float2 v2 = ((const float2*)(z0 + (size_t)s2 * COUT))[lane];
        float2 v3 = ((const float2*)(z0 + (size_t)s3 * COUT))[lane];
        acc.x += v0.x * w0 + v1.x * w1 + v2.x * w2 + v3.x * w3;
        acc.y += v0.y * w0 + v1.y * w1 + v2.y * w2 + v3.y * w3;
    }
    for (; j < n; j++) {
        int s0 = csr[base + j];
        float w0 = wcsr[base + j];
        float2 v0 = ((const float2*)(z0 + (size_t)s0 * COUT))[lane];
        acc.x += v0.x * w0; acc.y += v0.y * w0;
    }
    float idg = invdeg[node];
    float2 p = ((const float2*)(z0 + (size_t)node * COUT))[lane];
    float2 bv = ((const float2*)b2)[lane];
    float zx = fmaf(p.x, idg, acc.x) + bv.x;
    float zy = fmaf(p.y, idg, acc.y) + bv.y;
    __nv_bfloat162 z2 = __floats2bfloat162_rn(zx, zy);
    ((__nv_bfloat162*)(zb + (size_t)node * COUT))[lane] = z2;
    float2 zr = __bfloat1622float2(z2);  // rounded operand for GEMM3
    zrow[w][lane * 2 + 0] = zr.x;
    zrow[w][lane * 2 + 1] = zr.y;
    __syncwarp();
    // u[node][c] for c = lane, lane+32
    float a0 = 0.f, a1 = 0.f;
#pragma unroll 4
    for (int k = 0; k < COUT; k++) {
        float zk = zrow[w][k];
        a0 = fmaf(zk, Wbt[lane][k], a0);
        a1 = fmaf(zk, Wbt[lane + 32][k], a1);
    }
    ub[(size_t)node * COUT + lane] = __float2bfloat16_rn(a0);
    ub[(size_t)node * COUT + lane + 32] = __float2bfloat16_rn(a1);
}

// ------- decode: out[e] = sigmoid(dot(ub[src], zb[dst]) + bb), 8 lanes/edge -------
__global__ void k_edges(const int* __restrict__ s32, const int* __restrict__ d32,
                        const __nv_bfloat16* __restrict__ ub,
                        const __nv_bfloat16* __restrict__ zb, const float* __restrict__ bb,
                        float* __restrict__ out) {
    unsigned t = blockIdx.x * blockDim.x + threadIdx.x;
    unsigned e = t >> 3;
    int lane = t & 7;
    if (e >= NE) return;
    int s = s32[e];
    int d = d32[e];
    const __nv_bfloat162* ap = (const __nv_bfloat162*)(ub + (size_t)s * COUT) + lane * 4;
    const __nv_bfloat162* bp = (const __nv_bfloat162*)(zb + (size_t)d * COUT) + lane * 4;
    float p = 0.f;
#pragma unroll
    for (int j = 0; j < 4; j++) {
        float2 fa = __bfloat1622float2(ap[j]);
        float2 fb = __bfloat1622float2(bp[j]);
        p = fmaf(fa.x, fb.x, p);
        p = fmaf(fa.y, fb.y, p);
    }
    p += __shfl_xor_sync(0xffffffffu, p, 4);
    p += __shfl_xor_sync(0xffffffffu, p, 2);
    p += __shfl_xor_sync(0xffffffffu, p, 1);
    if (lane == 0) out[e] = 1.f / (1.f + expf(-(p + bb[0])));
}

extern "C" void kernel_launch(void* const* d_in, const int* in_sizes, int n_in,
                              void* d_out, int out_size) {
    const float* x  = (const float*)d_in[0];
    const void* ei  = d_in[1];
    const float* W1 = (const float*)d_in[2];
    const float* b1 = (const float*)d_in[3];
    const float* W2 = (const float*)d_in[4];
    const float* b2 = (const float*)d_in[5];
    const float* Wb = (const float*)d_in[6];
    const float* bb = (const float*)d_in[7];
    float* out      = (float*)d_out;

    int *cnt, *fpos, *tmp, *bsum, *s32, *d32, *csr, *is64p;
    float *wcsr, *dinv, *invdeg, *hW, *z0;
    __nv_bfloat16 *xb, *W1b, *zb, *ub;
    cudaGetSymbolAddress((void**)&cnt,   g_cnt);
    cudaGetSymbolAddress((void**)&fpos,  g_fpos);
    cudaGetSymbolAddress((void**)&tmp,   g_tmp);
    cudaGetSymbolAddress((void**)&bsum,  g_bsum);
    cudaGetSymbolAddress((void**)&s32,   g_s32);
    cudaGetSymbolAddress((void**)&d32,   g_d32);
    cudaGetSymbolAddress((void**)&csr,   g_csr);
    cudaGetSymbolAddress((void**)&wcsr,  g_wcsr);
    cudaGetSymbolAddress((void**)&dinv,  g_dinv);
    cudaGetSymbolAddress((void**)&invdeg,g_invdeg);
    cudaGetSymbolAddress((void**)&xb,    g_xb);
    cudaGetSymbolAddress((void**)&W1b,   g_W1b);
    cudaGetSymbolAddress((void**)&hW,    g_hW);
    cudaGetSymbolAddress((void**)&z0,    g_z0);
    cudaGetSymbolAddress((void**)&zb,    g_zb);
    cudaGetSymbolAddress((void**)&ub,    g_ub);
    cudaGetSymbolAddress((void**)&is64p, g_is64);

    const int T = 256;
    k_setup<<<(NN + T - 1) / T, T>>>((const int*)ei, cnt, fpos, is64p);
    k_prep<<<(NE + T - 1) / T, T>>>(ei, s32, d32, cnt, is64p);
    k_scan1<<<NB, 256>>>(cnt, tmp, bsum, dinv, invdeg);
    k_scan2<<<1, 256>>>(bsum);
    k_fill<<<(NE + T - 1) / T, T>>>(s32, d32, tmp, bsum, fpos, csr, wcsr, dinv);
    k_cvt8<<<(NN_PAD * CIN / 8 + T - 1) / T, T>>>(x, xb, NN * CIN, NN_PAD * CIN);
    k_cvtW1<<<(CIN * CHID + T - 1) / T, T>>>(W1, W1b);

    k_wgemm1<<<NN_PAD / 64, 128>>>(xb, W1b, hW);
    k_conv1<<<(NN * 32 + 255) / 256, 256>>>(tmp, bsum, cnt, csr, wcsr, hW, invdeg, b1, W2, z0);
    k_conv2<<<(NN * 32 + 255) / 256, 256>>>(tmp, bsum, cnt, csr, wcsr, z0, invdeg, b2, Wb, zb, ub);
    k_edges<<<(NE * 8 + T - 1) / T, T>>>(s32, d32, ub, zb, bb, out);
}

// round 15
// speedup vs baseline: 1.3644x; 1.3644x over previous
#include <cuda_runtime.h>
#include <cuda_bf16.h>
#include <mma.h>
using namespace nvcuda;

#define NN 50000
#define NN_PAD 50048   // 782 * 64
#define NE 800000
#define CIN 128
#define CHID 128
#define COUT 64
#define NB 196         // ceil(NN/256)

// ---------------- scratch (static device globals; host uses cudaGetSymbolAddress) ----------------
__device__ __align__(16) int   g_cnt[NN];
__device__ __align__(16) int   g_fpos[NN];
__device__ __align__(16) int   g_tmp[NN];
__device__ __align__(16) int   g_bsum[256];
__device__ __align__(16) int   g_s32[NE];
__device__ __align__(16) int   g_d32[NE];
__device__ __align__(16) int   g_csr[NE];
__device__ __align__(16) float g_wcsr[NE];
__device__ __align__(16) float g_dinv[NN];
__device__ __align__(16) float g_invdeg[NN];
__device__ __align__(16) __nv_bfloat16 g_xb[(size_t)NN_PAD * CIN];
__device__ __align__(16) __nv_bfloat16 g_W1b[CIN * CHID];
__device__ __align__(16) __nv_bfloat16 g_W2b[CHID * COUT];
__device__ __align__(16) __nv_bfloat16 g_Wbb[COUT * COUT];
__device__ __align__(16) float g_hW[(size_t)NN_PAD * CHID];          // x @ W1 (f32)
__device__ __align__(16) __nv_bfloat16 g_hb[(size_t)NN_PAD * CHID];  // bf16(relu h); pad stays 0
__device__ __align__(16) float g_z0[(size_t)NN_PAD * COUT];          // h @ W2 (f32)
__device__ __align__(16) __nv_bfloat16 g_zb[(size_t)NN_PAD * COUT];  // bf16(z); pad stays 0
__device__ __align__(16) __nv_bfloat16 g_ub[(size_t)NN_PAD * COUT];  // bf16(z @ Wb)
__device__ int g_is64;

__device__ __forceinline__ int eidx(const void* ei, unsigned idx, int is64) {
    if (is64) return (int)((const long long*)ei)[idx];
    return ((const int*)ei)[idx];
}

// ---------------- setup: probe dtype, zero counters, convert all weights ----------------
__global__ void k_setup(const int* __restrict__ ei32, const float* __restrict__ W1,
                        const float* __restrict__ W2, const float* __restrict__ Wb,
                        int* __restrict__ cnt, int* __restrict__ fpos,
                        __nv_bfloat16* __restrict__ W1b, __nv_bfloat16* __restrict__ W2b,
                        __nv_bfloat16* __restrict__ Wbb, int* __restrict__ is64p) {
    int i = blockIdx.x * blockDim.x + threadIdx.x;
    if (i == 0) {
        int is64 = 1;
        for (int k = 1; k < 128; k += 2)
            if (ei32[k] != 0) { is64 = 0; break; }
        *is64p = is64;
    }
    if (i < NN) { cnt[i] = 0; fpos[i] = 0; }
    if (i < CIN * CHID) W1b[i] = __float2bfloat16_rn(W1[i]);
    if (i < CHID * COUT) W2b[i] = __float2bfloat16_rn(W2[i]);
    if (i < COUT * COUT) Wbb[i] = __float2bfloat16_rn(Wb[i]);
}

// ---------------- prep: edge int32-ify + degree count + x -> bf16 (fused) ----------------
#define CVT_N (NN_PAD * CIN)          // 6406144
#define PREP_T ((CVT_N / 8 > NE) ? CVT_N / 8 : NE)   // 800768 threads

__global__ void k_prep(const void* __restrict__ ei, const float* __restrict__ x,
                       int* __restrict__ s32, int* __restrict__ d32,
                       int* __restrict__ cnt, __nv_bfloat16* __restrict__ xb,
                       const int* __restrict__ is64p) {
    int t = blockIdx.x * blockDim.x + threadIdx.x;
    if (t < NE) {
        int is64 = *is64p;
        int s = eidx(ei, t, is64);
        int d = eidx(ei, NE + t, is64);
        s32[t] = s;
        d32[t] = d;
        atomicAdd(&cnt[d], 1);
    }
    int base = t * 8;
    if (base < CVT_N) {
        uint4 o;
        if (base < NN * CIN) {
            float4 a = *(const float4*)(x + base);
            float4 b = *(const float4*)(x + base + 4);
            __nv_bfloat162 p0 = __floats2bfloat162_rn(a.x, a.y);
            __nv_bfloat162 p1 = __floats2bfloat162_rn(a.z, a.w);
            __nv_bfloat162 p2 = __floats2bfloat162_rn(b.x, b.y);
            __nv_bfloat162 p3 = __floats2bfloat162_rn(b.z, b.w);
            o.x = *(unsigned*)&p0; o.y = *(unsigned*)&p1;
            o.z = *(unsigned*)&p2; o.w = *(unsigned*)&p3;
        } else {
            o = make_uint4(0, 0, 0, 0);
        }
        *(uint4*)(xb + base) = o;
    }
}

// ---------------- scan: block-local exclusive + per-node dinv/invdeg ----------------
__global__ void k_scan1(const int* __restrict__ cnt, int* __restrict__ tmp,
                        int* __restrict__ bsum, float* __restrict__ dinv,
                        float* __restrict__ invdeg) {
    __shared__ int sh[256];
    int i = blockIdx.x * 256 + threadIdx.x;
    int v = (i < NN) ? cnt[i] : 0;
    if (i < NN) {
        float deg = (float)(v + 1);
        dinv[i] = rsqrtf(deg);
        invdeg[i] = 1.0f / deg;
    }
    sh[threadIdx.x] = v;
    __syncthreads();
    for (int off = 1; off < 256; off <<= 1) {
        int t = (threadIdx.x >= off) ? sh[threadIdx.x - off] : 0;
        __syncthreads();
        sh[threadIdx.x] += t;
        __syncthreads();
    }
    if (i < NN) tmp[i] = sh[threadIdx.x] - v;
    if (threadIdx.x == 255) bsum[blockIdx.x] = sh[255];
}

__global__ void k_scan2(int* __restrict__ bsum) {
    __shared__ int sh[256];
    int v = (threadIdx.x < NB) ? bsum[threadIdx.x] : 0;
    sh[threadIdx.x] = v;
    __syncthreads();
    for (int off = 1; off < 256; off <<= 1) {
        int t = (threadIdx.x >= off) ? sh[threadIdx.x - off] : 0;
        __syncthreads();
        sh[threadIdx.x] += t;
        __syncthreads();
    }
    if (threadIdx.x < NB) bsum[threadIdx.x] = sh[threadIdx.x] - v;
}

// ---------------- bucket-fill CSR (rp inline) + edge weight ----------------
__global__ void k_fill(const int* __restrict__ s32, const int* __restrict__ d32,
                       const int* __restrict__ tmp, const int* __restrict__ bsum,
                       int* __restrict__ fpos, int* __restrict__ csr,
                       float* __restrict__ wcsr, const float* __restrict__ dinv) {
    int e = blockIdx.x * blockDim.x + threadIdx.x;
    if (e >= NE) return;
    int s = s32[e];
    int d = d32[e];
    int rp = tmp[d] + bsum[d >> 8];
    int pos = rp + atomicAdd(&fpos[d], 1);
    csr[pos] = s;
    wcsr[pos] = dinv[s] * dinv[d];
}

// ------- tensor-core GEMM: A(bf16) @ W(bf16), f32 accum; optional direct bf16 output -------
template <int K, int NC, bool BF16OUT>
__global__ void k_wgemm(const __nv_bfloat16* __restrict__ A,
                        const __nv_bfloat16* __restrict__ W,
                        float* __restrict__ out, __nv_bfloat16* __restrict__ bout) {
    __shared__ __nv_bfloat16 Ws[K * NC];
    __shared__ float stage[BF16OUT ? 4 : 1][BF16OUT ? 16 * NC : 1];
    int tid = threadIdx.x;
    for (int i = tid * 8; i < K * NC; i += blockDim.x * 8)
        *(uint4*)(Ws + i) = *(const uint4*)(W + i);
    __syncthreads();
    int warp = tid >> 5;
    int lane = tid & 31;
    size_t row0 = (size_t)blockIdx.x * 64 + warp * 16;
    wmma::fragment<wmma::accumulator, 16, 16, 16, float> acc[NC / 16];
#pragma unroll
    for (int n = 0; n < NC / 16; n++) wmma::fill_fragment(acc[n], 0.f);
#pragma unroll
    for (int k0 = 0; k0 < K; k0 += 16) {
        wmma::fragment<wmma::matrix_a, 16, 16, 16, __nv_bfloat16, wmma::row_major> af;
        wmma::load_matrix_sync(af, A + row0 * K + k0, K);
#pragma unroll
        for (int n = 0; n < NC / 16; n++) {
            wmma::fragment<wmma::matrix_b, 16, 16, 16, __nv_bfloat16, wmma::row_major> bf;
            wmma::load_matrix_sync(bf, Ws + k0 * NC + n * 16, NC);
            wmma::mma_sync(acc[n], af, bf, acc[n]);
        }
    }
    if (BF16OUT) {
#pragma unroll
        for (int n = 0; n < NC / 16; n++)
            wmma::store_matrix_sync(stage[warp] + n * 16, acc[n], NC, wmma::mem_row_major);
        __syncwarp();
        __nv_bfloat162* gb = (__nv_bfloat162*)(bout + row0 * NC);
        for (int i = lane; i < 16 * NC / 2; i += 32) {
            float2 f = ((const float2*)stage[warp])[i];
            gb[i] = __floats2bfloat162_rn(f.x, f.y);
        }
    } else {
#pragma unroll
        for (int n = 0; n < NC / 16; n++)
            wmma::store_matrix_sync(out + row0 * NC + n * 16, acc[n], NC, wmma::mem_row_major);
    }
}

// ------- CSR gather + finalize, 128ch: one warp per node, unroll 4 -> bf16 -------
__global__ void k_gather128(const int* __restrict__ tmp, const int* __restrict__ bsum,
                            const int* __restrict__ cnt, const int* __restrict__ csr,
                            const float* __restrict__ wcsr, const float* __restrict__ hW,
                            const float* __restrict__ invdeg, const float* __restrict__ b,
                            __nv_bfloat16* __restrict__ bout) {
    int warp = (blockIdx.x * blockDim.x + threadIdx.x) >> 5;
    int lane = threadIdx.x & 31;
    if (warp >= NN) return;
    int node = warp;
    int n = cnt[node];
    int base = tmp[node] + bsum[node >> 8];
    float4 acc = make_float4(0.f, 0.f, 0.f, 0.f);
    int j = 0;
    for (; j + 4 <= n; j += 4) {
        int s0 = csr[base + j],     s1 = csr[base + j + 1];
        int s2 = csr[base + j + 2], s3 = csr[base + j + 3];
        float w0 = wcsr[base + j],     w1 = wcsr[base + j + 1];
        float w2 = wcsr[base + j + 2], w3 = wcsr[base + j + 3];
        float4 v0 = ((const float4*)(hW + (size_t)s0 * CHID))[lane];
        float4 v1 = ((const float4*)(hW + (size_t)s1 * CHID))[lane];
        float4 v2 = ((const float4*)(hW + (size_t)s2 * CHID))[lane];
        float4 v3 = ((const float4*)(hW + (size_t)s3 * CHID))[lane];
        acc.x += v0.x * w0 + v1.x * w1 + v2.x * w2 + v3.x * w3;
        acc.y += v0.y * w0 + v1.y * w1 + v2.y * w2 + v3.y * w3;
        acc.z += v0.z * w0 + v1.z * w1 + v2.z * w2 + v3.z * w3;
        acc.w += v0.w * w0 + v1.w * w1 + v2.w * w2 + v3.w * w3;
    }
    for (; j < n; j++) {
        int s0 = csr[base + j];
        float w0 = wcsr[base + j];
        float4 v0 = ((const float4*)(hW + (size_t)s0 * CHID))[lane];
        acc.x += v0.x * w0; acc.y += v0.y * w0;
        acc.z += v0.z * w0; acc.w += v0.w * w0;
    }
    float idg = invdeg[node];
    float4 p = ((const float4*)(hW + (size_t)node * CHID))[lane];
    float4 bv = ((const float4*)b)[lane];
    float ox = fmaxf(fmaf(p.x, idg, acc.x) + bv.x, 0.f);
    float oy = fmaxf(fmaf(p.y, idg, acc.y) + bv.y, 0.f);
    float oz = fmaxf(fmaf(p.z, idg, acc.z) + bv.z, 0.f);
    float ow = fmaxf(fmaf(p.w, idg, acc.w) + bv.w, 0.f);
    __nv_bfloat162 lo = __floats2bfloat162_rn(ox, oy);
    __nv_bfloat162 hi = __floats2bfloat162_rn(oz, ow);
    ((__nv_bfloat162*)(bout + (size_t)node * CHID))[lane * 2] = lo;
    ((__nv_bfloat162*)(bout + (size_t)node * CHID))[lane * 2 + 1] = hi;
}

// ------- CSR gather + finalize, 64ch (no relu): one warp per node, unroll 4 -> bf16 -------
__global__ void k_gather64(const int* __restrict__ tmp, const int* __restrict__ bsum,
                           const int* __restrict__ cnt, const int* __restrict__ csr,
                           const float* __restrict__ wcsr, const float* __restrict__ z0,
                           const float* __restrict__ invdeg, const float* __restrict__ b,
                           __nv_bfloat16* __restrict__ bout) {
    int warp = (blockIdx.x * blockDim.x + threadIdx.x) >> 5;
    int lane = threadIdx.x & 31;
    if (warp >= NN) return;
    int node = warp;
    int n = cnt[node];
    int base = tmp[node] + bsum[node >> 8];
    float2 acc = make_float2(0.f, 0.f);
    int j = 0;
    for (; j + 4 <= n; j += 4) {
        int s0 = csr[base + j],     s1 = csr[base + j + 1];
        int s2 = csr[base + j + 2], s3 = csr[base + j + 3];
        float w0 = wcsr[base + j],     w1 = wcsr[base + j + 1];
        float w2 = wcsr[base + j + 2], w3 = wcsr[base + j + 3];
        float2 v0 = ((const float2*)(z0 + (size_t)s0 * COUT))[lane];
        float2 v1 = ((const float2*)(z0 + (size_t)s1 * COUT))[lane];
        float2 v2 = ((const float2*)(z0 + (size_t)s2 * COUT))[lane];
        float2 v3 = ((const float2*)(z0 + (size_t)s3 * COUT))[lane];
        acc.x += v0.x * w0 + v1.x * w1 + v2.x * w2 + v3.x * w3;
        acc.y += v0.y * w0 + v1.y * w1 + v2.y * w2 + v3.y * w3;
    }
    for (; j < n; j++) {
        int s0 = csr[base + j];
        float w0 = wcsr[base + j];
        float2 v0 = ((const float2*)(z0 + (size_t)s0 * COUT))[lane];
        acc.x += v0.x * w0; acc.y += v0.y * w0;
    }
    float idg = invdeg[node];
    float2 p = ((const float2*)(z0 + (size_t)node * COUT))[lane];
    float2 bv = ((const float2*)b)[lane];
    float ox = fmaf(p.x, idg, acc.x) + bv.x;
    float oy = fmaf(p.y, idg, acc.y) + bv.y;
    ((__nv_bfloat162*)(bout + (size_t)node * COUT))[lane] = __floats2bfloat162_rn(ox, oy);
}

// ------- decode: out[e] = sigmoid(dot(ub[src], zb[dst]) + bb), 8 lanes/edge -------
__global__ void k_edges(const int* __restrict__ s32, const int* __restrict__ d32,
                        const __nv_bfloat16* __restrict__ ub,
                        const __nv_bfloat16* __restrict__ zb, const float* __restrict__ bb,
                        float* __restrict__ out) {
    unsigned t = blockIdx.x * blockDim.x + threadIdx.x;
    unsigned e = t >> 3;
    int lane = t & 7;
    if (e >= NE) return;
    int s = s32[e];
    int d = d32[e];
    const __nv_bfloat162* ap = (const __nv_bfloat162*)(ub + (size_t)s * COUT) + lane * 4;
    const __nv_bfloat162* bp = (const __nv_bfloat162*)(zb + (size_t)d * COUT) + lane * 4;
    float p = 0.f;
#pragma unroll
    for (int j = 0; j < 4; j++) {
        float2 fa = __bfloat1622float2(ap[j]);
        float2 fb = __bfloat1622float2(bp[j]);
        p = fmaf(fa.x, fb.x, p);
        p = fmaf(fa.y, fb.y, p);
    }
    p += __shfl_xor_sync(0xffffffffu, p, 4);
    p += __shfl_xor_sync(0xffffffffu, p, 2);
    p += __shfl_xor_sync(0xffffffffu, p, 1);
    if (lane == 0) out[e] = 1.f / (1.f + expf(-(p + bb[0])));
}

extern "C" void kernel_launch(void* const* d_in, const int* in_sizes, int n_in,
                              void* d_out, int out_size) {
    const float* x  = (const float*)d_in[0];
    const void* ei  = d_in[1];
    const float* W1 = (const float*)d_in[2];
    const float* b1 = (const float*)d_in[3];
    const float* W2 = (const float*)d_in[4];
    const float* b2 = (const float*)d_in[5];
    const float* Wb = (const float*)d_in[6];
    const float* bb = (const float*)d_in[7];
    float* out      = (float*)d_out;

    int *cnt, *fpos, *tmp, *bsum, *s32, *d32, *csr, *is64p;
    float *wcsr, *dinv, *invdeg, *hW, *z0;
    __nv_bfloat16 *xb, *W1b, *W2b, *Wbb, *hb, *zb, *ub;
    cudaGetSymbolAddress((void**)&cnt,   g_cnt);
    cudaGetSymbolAddress((void**)&fpos,  g_fpos);
    cudaGetSymbolAddress((void**)&tmp,   g_tmp);
    cudaGetSymbolAddress((void**)&bsum,  g_bsum);
    cudaGetSymbolAddress((void**)&s32,   g_s32);
    cudaGetSymbolAddress((void**)&d32,   g_d32);
    cudaGetSymbolAddress((void**)&csr,   g_csr);
    cudaGetSymbolAddress((void**)&wcsr,  g_wcsr);
    cudaGetSymbolAddress((void**)&dinv,  g_dinv);
    cudaGetSymbolAddress((void**)&invdeg,g_invdeg);
    cudaGetSymbolAddress((void**)&xb,    g_xb);
    cudaGetSymbolAddress((void**)&W1b,   g_W1b);
    cudaGetSymbolAddress((void**)&W2b,   g_W2b);
    cudaGetSymbolAddress((void**)&Wbb,   g_Wbb);
    cudaGetSymbolAddress((void**)&hW,    g_hW);
    cudaGetSymbolAddress((void**)&hb,    g_hb);
    cudaGetSymbolAddress((void**)&z0,    g_z0);
    cudaGetSymbolAddress((void**)&zb,    g_zb);
    cudaGetSymbolAddress((void**)&ub,    g_ub);
    cudaGetSymbolAddress((void**)&is64p, g_is64);

    const int T = 256;
    k_setup<<<(NN + T - 1) / T, T>>>((const int*)ei, W1, W2, Wb, cnt, fpos,
                                     W1b, W2b, Wbb, is64p);
    k_prep<<<(PREP_T + T - 1) / T, T>>>(ei, x, s32, d32, cnt, xb, is64p);
    k_scan1<<<NB, 256>>>(cnt, tmp, bsum, dinv, invdeg);
    k_scan2<<<1, 256>>>(bsum);
    k_fill<<<(NE + T - 1) / T, T>>>(s32, d32, tmp, bsum, fpos, csr, wcsr, dinv);

    k_wgemm<CIN, CHID, false><<<NN_PAD / 64, 128>>>(xb, W1b, hW, nullptr);
    k_gather128<<<(NN * 32 + T - 1) / T, T>>>(tmp, bsum, cnt, csr, wcsr, hW, invdeg, b1, hb);

    k_wgemm<CHID, COUT, false><<<NN_PAD / 64, 128>>>(hb, W2b, z0, nullptr);
    k_gather64<<<(NN * 32 + T - 1) / T, T>>>(tmp, bsum, cnt, csr, wcsr, z0, invdeg, b2, zb);

    k_wgemm<COUT, COUT, true><<<NN_PAD / 64, 128>>>(zb, Wbb, nullptr, ub);
    k_edges<<<(NE * 8 + T - 1) / T, T>>>(s32, d32, ub, zb, bb, out);
}